// round 7
// baseline (speedup 1.0000x reference)
#include <cuda_runtime.h>

// Problem constants
#define BB      512      // batch
#define INU     8        // in_units (k)
#define INCH    1152     // in_channels (i)
#define NU      10       // num_units (j)
#define US      16       // unit_size (u)
#define JU      160      // NU*US
#define KI      9216     // INU*INCH
#define BETA    1.45f
#define KSPLIT  72
#define KCHUNK  128      // KI / KSPLIT  (divides INCH: 1152 = 9*128)
#define MT      128      // gemm M tile
#define BSPLIT  4        // gemm2 batch split
#define BCHUNK  (BB / BSPLIT)

// dynamic smem: As (2 x 16 x 128 float) then Bs2 (2 x 16 x 160 float2, duplicated)
#define AS_BYTES  (2 * 16 * MT * 4)       // 16384
#define BS2_BYTES (2 * 16 * JU * 8)       // 40960
#define SMEM_SZ   (AS_BYTES + BS2_BYTES)  // 57344

// Scratch (device globals -- no allocation allowed)
__device__ float g_Wt[KI * JU];                 // Wt[k*INCH+i][ju] = W[i,j,u,k]
__device__ float g_Gpart[BSPLIT][KI * JU];      // batch-split partials of G = x^T @ v
__device__ float g_spart[KSPLIT * BB * JU];
__device__ float g_s[BB * JU];
__device__ float g_v[BB * JU];
__device__ float g_b[INCH * NU];
__device__ float g_c[INCH * NU];

// ---- packed fp32x2 helper ---------------------------------------------------
__device__ __forceinline__ void ffma2(unsigned long long& d,
                                      unsigned long long a, unsigned long long b) {
    asm("fma.rn.f32x2 %0, %1, %2, %0;" : "+l"(d) : "l"(a), "l"(b));
}

// ---------------------------------------------------------------------------
__global__ void zero_b_k() {
    int idx = blockIdx.x * blockDim.x + threadIdx.x;
    if (idx < INCH * NU) g_b[idx] = 0.0f;
}

// Wt[(k*INCH+i)*JU + ju] = W[(i*JU+ju)*INU + k]
__global__ void transposeW_k(const float* __restrict__ W) {
    int idx = blockIdx.x * blockDim.x + threadIdx.x;   // over INCH*JU
    if (idx >= INCH * JU) return;
    int i = idx / JU;
    int ju = idx - i * JU;
    float4 w0 = *reinterpret_cast<const float4*>(&W[idx * 8]);
    float4 w1 = *reinterpret_cast<const float4*>(&W[idx * 8 + 4]);
    g_Wt[(0 * INCH + i) * JU + ju] = w0.x;
    g_Wt[(1 * INCH + i) * JU + ju] = w0.y;
    g_Wt[(2 * INCH + i) * JU + ju] = w0.z;
    g_Wt[(3 * INCH + i) * JU + ju] = w0.w;
    g_Wt[(4 * INCH + i) * JU + ju] = w1.x;
    g_Wt[(5 * INCH + i) * JU + ju] = w1.y;
    g_Wt[(6 * INCH + i) * JU + ju] = w1.z;
    g_Wt[(7 * INCH + i) * JU + ju] = w1.w;
}

// softmax over i (axis 0) for each column j of g_b (INCH x NU)
__global__ void softmax_k() {
    int j = blockIdx.x;
    __shared__ float red[128];
    int t = threadIdx.x;
    float mx = -1e30f;
    for (int i = t; i < INCH; i += 128) mx = fmaxf(mx, g_b[i * NU + j]);
    red[t] = mx; __syncthreads();
    for (int o = 64; o > 0; o >>= 1) {
        if (t < o) red[t] = fmaxf(red[t], red[t + o]);
        __syncthreads();
    }
    mx = red[0]; __syncthreads();
    float sum = 0.0f;
    for (int i = t; i < INCH; i += 128) sum += __expf(g_b[i * NU + j] - mx);
    red[t] = sum; __syncthreads();
    for (int o = 64; o > 0; o >>= 1) {
        if (t < o) red[t] += red[t + o];
        __syncthreads();
    }
    float inv = 1.0f / red[0];
    for (int i = t; i < INCH; i += 128)
        g_c[i * NU + j] = __expf(g_b[i * NU + j] - mx) * inv;
}

// ===========================================================================
// GEMM1: s_part = x(512 x 9216) @ (c ⊙ Wt)(9216 x 160), split-K, pipelined.
// Block tile 128(M) x 160(N), 256 threads, micro 8x10 with M-paired FFMA2:
// A read as natural float pairs, B pre-duplicated (b,b) in smem. No MOVs.
__global__ __launch_bounds__(256, 2) void gemm1_k(const float* __restrict__ x) {
    extern __shared__ char smem[];
    float  (*As)[16][MT]  = reinterpret_cast<float(*)[16][MT]>(smem);
    float2 (*Bs2)[16][JU] = reinterpret_cast<float2(*)[16][JU]>(smem + AS_BYTES);

    const int m0 = blockIdx.x * MT;
    const int kbase0 = blockIdx.y * KCHUNK;
    const int i0 = kbase0 % INCH;                // chunk never crosses a k-slice
    const int tid = threadIdx.x;
    const int trow = tid >> 4;                   // 0..15
    const int tcol = tid & 15;                   // 0..15
    const int nb = tcol * 10;
    const int j0 = nb >> 4;
    const int j1 = (nb + 9) >> 4;
    const int aRow = tid >> 1;                   // 0..127
    const int aCol = (tid & 1) * 8;              // 0 or 8
    const int bRow = tid >> 4;                   // 0..15

    // acc[r][c]: u64 = rows (trow*8+2r, trow*8+2r+1), col nb+c
    unsigned long long acc[4][10];
#pragma unroll
    for (int r = 0; r < 4; r++)
#pragma unroll
        for (int c = 0; c < 10; c++) acc[r][c] = 0ULL;

    float4 rA0, rA1;
    float2 rB[5];
    float rc0, rc1;

#define G1_FETCH(ks)                                                              \
    {                                                                             \
        const float* ap = &x[(m0 + aRow) * KI + kbase0 + (ks) + aCol];            \
        rA0 = *reinterpret_cast<const float4*>(ap);                               \
        rA1 = *reinterpret_cast<const float4*>(ap + 4);                           \
        const float* bp = &g_Wt[(kbase0 + (ks) + bRow) * JU + nb];                \
        rB[0] = *reinterpret_cast<const float2*>(bp + 0);                         \
        rB[1] = *reinterpret_cast<const float2*>(bp + 2);                         \
        rB[2] = *reinterpret_cast<const float2*>(bp + 4);                         \
        rB[3] = *reinterpret_cast<const float2*>(bp + 6);                         \
        rB[4] = *reinterpret_cast<const float2*>(bp + 8);                         \
        const float* cp = &g_c[(i0 + (ks) + bRow) * NU];                          \
        rc0 = cp[j0];                                                             \
        rc1 = cp[j1];                                                             \
    }

#define G1_STORE(buf)                                                             \
    {                                                                             \
        As[buf][aCol + 0][aRow] = rA0.x;                                          \
        As[buf][aCol + 1][aRow] = rA0.y;                                          \
        As[buf][aCol + 2][aRow] = rA0.z;                                          \
        As[buf][aCol + 3][aRow] = rA0.w;                                          \
        As[buf][aCol + 4][aRow] = rA1.x;                                          \
        As[buf][aCol + 5][aRow] = rA1.y;                                          \
        As[buf][aCol + 6][aRow] = rA1.z;                                          \
        As[buf][aCol + 7][aRow] = rA1.w;                                          \
        _Pragma("unroll")                                                         \
        for (int c = 0; c < 5; c++) {                                             \
            float wx = rB[c].x * (((nb + 2 * c) >> 4) == j0 ? rc0 : rc1);         \
            float wy = rB[c].y * (((nb + 2 * c + 1) >> 4) == j0 ? rc0 : rc1);     \
            Bs2[buf][bRow][nb + 2 * c]     = make_float2(wx, wx);                 \
            Bs2[buf][bRow][nb + 2 * c + 1] = make_float2(wy, wy);                 \
        }                                                                         \
    }

    G1_FETCH(0);
    G1_STORE(0);
    __syncthreads();

#pragma unroll 1
    for (int t = 0; t < KCHUNK / 16; t++) {
        const int buf = t & 1;
        if (t + 1 < KCHUNK / 16) G1_FETCH((t + 1) * 16);
#pragma unroll
        for (int kk = 0; kk < 16; kk++) {
            // A: 8 consecutive floats = 4 natural u64 pairs (broadcast LDS.128)
            const ulonglong2* ar =
                reinterpret_cast<const ulonglong2*>(&As[buf][kk][trow * 8]);
            ulonglong2 aa = ar[0];
            ulonglong2 ab = ar[1];
            unsigned long long ap0 = aa.x, ap1 = aa.y, ap2 = ab.x, ap3 = ab.y;
            const ulonglong2* br =
                reinterpret_cast<const ulonglong2*>(&Bs2[buf][kk][nb]);
#pragma unroll
            for (int cc = 0; cc < 5; cc++) {
                ulonglong2 bb = br[cc];            // (b[2cc],b[2cc]), (b[2cc+1],b[2cc+1])
                ffma2(acc[0][2 * cc], ap0, bb.x);
                ffma2(acc[1][2 * cc], ap1, bb.x);
                ffma2(acc[2][2 * cc], ap2, bb.x);
                ffma2(acc[3][2 * cc], ap3, bb.x);
                ffma2(acc[0][2 * cc + 1], ap0, bb.y);
                ffma2(acc[1][2 * cc + 1], ap1, bb.y);
                ffma2(acc[2][2 * cc + 1], ap2, bb.y);
                ffma2(acc[3][2 * cc + 1], ap3, bb.y);
            }
        }
        if (t + 1 < KCHUNK / 16) {
            G1_STORE(buf ^ 1);
            __syncthreads();
        }
    }

    float* out = &g_spart[blockIdx.y * (BB * JU)];
#pragma unroll
    for (int r = 0; r < 4; r++)
#pragma unroll
        for (int c = 0; c < 10; c++) {
            float2 f = *reinterpret_cast<float2*>(&acc[r][c]);
            out[(m0 + trow * 8 + 2 * r) * JU + nb + c] = f.x;
            out[(m0 + trow * 8 + 2 * r + 1) * JU + nb + c] = f.y;
        }
#undef G1_FETCH
#undef G1_STORE
}

// reduce split-K partials: s = sum over KSPLIT of s_part (float4, coalesced)
__global__ void reduceS_k() {
    int idx = blockIdx.x * blockDim.x + threadIdx.x;   // over BB*JU/4
    if (idx >= BB * JU / 4) return;
    float4 acc = make_float4(0.f, 0.f, 0.f, 0.f);
#pragma unroll 8
    for (int ks = 0; ks < KSPLIT; ks++) {
        float4 v = *reinterpret_cast<const float4*>(&g_spart[ks * (BB * JU) + idx * 4]);
        acc.x += v.x; acc.y += v.y; acc.z += v.z; acc.w += v.w;
    }
    *reinterpret_cast<float4*>(&g_s[idx * 4]) = acc;
}

// squash: mag_sq over j (num_units axis). Writes g_v, optionally also d_out.
__global__ void squash_k(float* __restrict__ out, int writeOut) {
    int idx = blockIdx.x * blockDim.x + threadIdx.x;   // (b,u): 512*16
    if (idx >= BB * US) return;
    int b = idx >> 4;
    int u = idx & 15;
    float sv[NU];
    float msq = 0.0f;
#pragma unroll
    for (int j = 0; j < NU; j++) {
        sv[j] = g_s[b * JU + j * US + u];
        msq += sv[j] * sv[j];
    }
    float mag = sqrtf(msq);
    float sc = msq / ((BETA + msq) * mag);
    if (writeOut) {
#pragma unroll
        for (int j = 0; j < NU; j++) out[b * JU + j * US + u] = sc * sv[j];
    } else {
#pragma unroll
        for (int j = 0; j < NU; j++) g_v[b * JU + j * US + u] = sc * sv[j];
    }
}

// ===========================================================================
// GEMM2: Gpart[s] = x^T chunk (9216 x BCHUNK) @ v chunk (BCHUNK x 160).
// Same M-paired FFMA2 structure; A layout already natural (no transpose needed).
__global__ __launch_bounds__(256, 2) void gemm2_k(const float* __restrict__ x) {
    extern __shared__ char smem[];
    float  (*As)[16][MT]  = reinterpret_cast<float(*)[16][MT]>(smem);
    float2 (*Bs2)[16][JU] = reinterpret_cast<float2(*)[16][JU]>(smem + AS_BYTES);

    const int m0 = blockIdx.x * MT;            // over KI
    const int kb0 = blockIdx.y * BCHUNK;       // batch chunk
    const int tid = threadIdx.x;
    const int trow = tid >> 4;
    const int tcol = tid & 15;
    const int nb = tcol * 10;
    const int aK = tid >> 5;                   // 0..7  (rows aK and aK+8)
    const int aM = (tid & 31) * 4;
    const int bRow = tid >> 4;

    unsigned long long acc[4][10];
#pragma unroll
    for (int r = 0; r < 4; r++)
#pragma unroll
        for (int c = 0; c < 10; c++) acc[r][c] = 0ULL;

    float4 rA0, rA1;
    float2 rB[5];

#define G2_FETCH(kb)                                                              \
    {                                                                             \
        rA0 = *reinterpret_cast<const float4*>(&x[((kb) + aK) * KI + m0 + aM]);   \
        rA1 = *reinterpret_cast<const float4*>(&x[((kb) + aK + 8) * KI + m0 + aM]);\
        const float* bp = &g_v[((kb) + bRow) * JU + nb];                          \
        rB[0] = *reinterpret_cast<const float2*>(bp + 0);                         \
        rB[1] = *reinterpret_cast<const float2*>(bp + 2);                         \
        rB[2] = *reinterpret_cast<const float2*>(bp + 4);                         \
        rB[3] = *reinterpret_cast<const float2*>(bp + 6);                         \
        rB[4] = *reinterpret_cast<const float2*>(bp + 8);                         \
    }

#define G2_STORE(buf)                                                             \
    {                                                                             \
        *reinterpret_cast<float4*>(&As[buf][aK][aM]) = rA0;                       \
        *reinterpret_cast<float4*>(&As[buf][aK + 8][aM]) = rA1;                   \
        _Pragma("unroll")                                                         \
        for (int c = 0; c < 5; c++) {                                             \
            Bs2[buf][bRow][nb + 2 * c]     = make_float2(rB[c].x, rB[c].x);       \
            Bs2[buf][bRow][nb + 2 * c + 1] = make_float2(rB[c].y, rB[c].y);       \
        }                                                                         \
    }

    G2_FETCH(kb0);
    G2_STORE(0);
    __syncthreads();

#pragma unroll 1
    for (int t = 0; t < BCHUNK / 16; t++) {
        const int buf = t & 1;
        if (t + 1 < BCHUNK / 16) G2_FETCH(kb0 + (t + 1) * 16);
#pragma unroll
        for (int kk = 0; kk < 16; kk++) {
            const ulonglong2* ar =
                reinterpret_cast<const ulonglong2*>(&As[buf][kk][trow * 8]);
            ulonglong2 aa = ar[0];
            ulonglong2 ab = ar[1];
            unsigned long long ap0 = aa.x, ap1 = aa.y, ap2 = ab.x, ap3 = ab.y;
            const ulonglong2* br =
                reinterpret_cast<const ulonglong2*>(&Bs2[buf][kk][nb]);
#pragma unroll
            for (int cc = 0; cc < 5; cc++) {
                ulonglong2 bb = br[cc];
                ffma2(acc[0][2 * cc], ap0, bb.x);
                ffma2(acc[1][2 * cc], ap1, bb.x);
                ffma2(acc[2][2 * cc], ap2, bb.x);
                ffma2(acc[3][2 * cc], ap3, bb.x);
                ffma2(acc[0][2 * cc + 1], ap0, bb.y);
                ffma2(acc[1][2 * cc + 1], ap1, bb.y);
                ffma2(acc[2][2 * cc + 1], ap2, bb.y);
                ffma2(acc[3][2 * cc + 1], ap3, bb.y);
            }
        }
        if (t + 1 < BCHUNK / 16) {
            G2_STORE(buf ^ 1);
            __syncthreads();
        }
    }

    float* out = g_Gpart[blockIdx.y];
#pragma unroll
    for (int r = 0; r < 4; r++)
#pragma unroll
        for (int c = 0; c < 10; c++) {
            float2 f = *reinterpret_cast<float2*>(&acc[r][c]);
            out[(m0 + trow * 8 + 2 * r) * JU + nb + c] = f.x;
            out[(m0 + trow * 8 + 2 * r + 1) * JU + nb + c] = f.y;
        }
#undef G2_FETCH
#undef G2_STORE
}

// b[i,j] = (1/B) * sum_{k,u} Wt[(k*INCH+i)*JU + j*US+u] * (ΣGpart)[same]
__global__ void bupdate_k() {
    int gw = (blockIdx.x * blockDim.x + threadIdx.x) >> 5;
    int lane = threadIdx.x & 31;
    if (gw >= INCH * NU) return;
    int i = gw / NU;
    int j = gw - i * NU;
    int k = lane >> 2;
    int u = (lane & 3) * 4;
    int idx = (k * INCH + i) * JU + j * US + u;
    float4 w = *reinterpret_cast<const float4*>(&g_Wt[idx]);
    float4 g = *reinterpret_cast<const float4*>(&g_Gpart[0][idx]);
#pragma unroll
    for (int s = 1; s < BSPLIT; s++) {
        float4 gs = *reinterpret_cast<const float4*>(&g_Gpart[s][idx]);
        g.x += gs.x; g.y += gs.y; g.z += gs.z; g.w += gs.w;
    }
    float acc = w.x * g.x + w.y * g.y + w.z * g.z + w.w * g.w;
#pragma unroll
    for (int o = 16; o > 0; o >>= 1) acc += __shfl_xor_sync(0xffffffffu, acc, o);
    if (lane == 0) g_b[i * NU + j] = acc * (1.0f / (float)BB);
}

// ---------------------------------------------------------------------------
extern "C" void kernel_launch(void* const* d_in, const int* in_sizes, int n_in,
                              void* d_out, int out_size) {
    const float* x = (const float*)d_in[0];
    const float* W = (const float*)d_in[1];
    if (n_in >= 2 && in_sizes[0] == INCH * NU * US * INU) {
        const float* t = x; x = W; W = t;
    }
    float* out = (float*)d_out;

    cudaFuncSetAttribute(gemm1_k, cudaFuncAttributeMaxDynamicSharedMemorySize, SMEM_SZ);
    cudaFuncSetAttribute(gemm2_k, cudaFuncAttributeMaxDynamicSharedMemorySize, SMEM_SZ);

    zero_b_k<<<(INCH * NU + 255) / 256, 256>>>();
    transposeW_k<<<(INCH * JU + 255) / 256, 256>>>(W);

    for (int t = 0; t < 3; t++) {
        softmax_k<<<NU, 128>>>();
        gemm1_k<<<dim3(BB / MT, KSPLIT), 256, SMEM_SZ>>>(x);
        reduceS_k<<<(BB * JU / 4 + 127) / 128, 128>>>();
        squash_k<<<(BB * US + 255) / 256, 256>>>(out, t == 2 ? 1 : 0);
        if (t < 2) {
            gemm2_k<<<dim3(KI / MT, BSPLIT), 256, SMEM_SZ>>>(x);
            bupdate_k<<<(INCH * NU * 32) / 256, 256>>>();
        }
    }
}

// round 10
// speedup vs baseline: 1.8825x; 1.8825x over previous
#include <cuda_runtime.h>
#include <cuda_bf16.h>
#include <cstdint>

// Problem constants
#define BB      512      // batch
#define INU     8        // in_units (k)
#define INCH    1152     // in_channels (i)
#define NU      10       // num_units (j)
#define US      16       // unit_size (u)
#define JU      160      // NU*US
#define KI      9216     // INU*INCH
#define BETA    1.45f
#define KSPLIT  72
#define KCH     128      // fp32 K per chunk (KI/KSPLIT); bf16 K' = 384 (3 products)
#define MT      128      // gemm2 M tile
#define BSPLIT  4        // gemm2 batch split
#define BCHUNK  (BB / BSPLIT)

// gemm1 smem: A' [128][KP] bf16, B' [160][KP] bf16, KP = 384 + 8 pad
#define KP        392
#define KSTEPS    24                          // 384 / 16
#define ASM_BYTES (128 * KP * 2)              // 100352
#define SMEM_G1   (ASM_BYTES + 160 * KP * 2)  // 225792

// Scratch (device globals -- no allocation allowed)
__device__ float g_Wt[KI * JU];                 // [ki][ju]  (bupdate)
__device__ float g_Wtt[JU * KI];                // [ju][ki]  (gemm1 B loads)
__device__ float g_Gpart[BSPLIT][KI * JU];
__device__ float g_spart[KSPLIT * BB * JU];     // [chunk][b][ju]
__device__ float g_s[BB * JU];
__device__ float g_v[BB * JU];
__device__ float g_b[INCH * NU];
__device__ float g_c[INCH * NU];

// ---- warp-mma helpers ------------------------------------------------------
__device__ __forceinline__ uint32_t s2u(const void* p) {
    uint32_t a;
    asm("{ .reg .u64 t; cvta.to.shared.u64 t, %1; cvt.u32.u64 %0, t; }" : "=r"(a) : "l"(p));
    return a;
}
__device__ __forceinline__ void ldm_x4(uint32_t* r, uint32_t addr) {
    asm volatile("ldmatrix.sync.aligned.m8n8.x4.shared.b16 {%0,%1,%2,%3}, [%4];"
                 : "=r"(r[0]), "=r"(r[1]), "=r"(r[2]), "=r"(r[3]) : "r"(addr));
}
__device__ __forceinline__ void mma16816(float* d, const uint32_t* a, const uint32_t* b) {
    asm volatile("mma.sync.aligned.m16n8k16.row.col.f32.bf16.bf16.f32 "
                 "{%0,%1,%2,%3}, {%4,%5,%6,%7}, {%8,%9}, {%0,%1,%2,%3};"
                 : "+f"(d[0]), "+f"(d[1]), "+f"(d[2]), "+f"(d[3])
                 : "r"(a[0]), "r"(a[1]), "r"(a[2]), "r"(a[3]), "r"(b[0]), "r"(b[1]));
}
__device__ __forceinline__ void split_bf16(float v, __nv_bfloat16& h, __nv_bfloat16& l) {
    h = __float2bfloat16_rn(v);
    l = __float2bfloat16_rn(v - __bfloat162float(h));
}

// ---- packed fp32x2 helpers (gemm2) -----------------------------------------
__device__ __forceinline__ unsigned long long pk2(float v) {
    unsigned long long r;
    asm("mov.b64 %0, {%1, %1};" : "=l"(r) : "f"(v));
    return r;
}
__device__ __forceinline__ void ffma2(unsigned long long& d,
                                      unsigned long long a, unsigned long long b) {
    asm("fma.rn.f32x2 %0, %1, %2, %0;" : "+l"(d) : "l"(a), "l"(b));
}

// ---------------------------------------------------------------------------
__global__ void zero_b_k() {
    int idx = blockIdx.x * blockDim.x + threadIdx.x;
    if (idx < INCH * NU) g_b[idx] = 0.0f;
}

// g_Wt[(k*INCH+i)*JU + ju] and g_Wtt[ju*KI + k*INCH+i] from W[(i*JU+ju)*INU + k]
__global__ void transposeW_k(const float* __restrict__ W) {
    int idx = blockIdx.x * blockDim.x + threadIdx.x;   // over INCH*JU
    if (idx >= INCH * JU) return;
    int i = idx / JU;
    int ju = idx - i * JU;
    float4 w0 = *reinterpret_cast<const float4*>(&W[idx * 8]);
    float4 w1 = *reinterpret_cast<const float4*>(&W[idx * 8 + 4]);
    float w[8] = {w0.x, w0.y, w0.z, w0.w, w1.x, w1.y, w1.z, w1.w};
#pragma unroll
    for (int k = 0; k < 8; k++) {
        g_Wt[(k * INCH + i) * JU + ju] = w[k];
        g_Wtt[ju * KI + k * INCH + i] = w[k];
    }
}

// softmax over i (axis 0) for each column j of g_b (INCH x NU)
__global__ void softmax_k() {
    int j = blockIdx.x;
    __shared__ float red[128];
    int t = threadIdx.x;
    float mx = -1e30f;
    for (int i = t; i < INCH; i += 128) mx = fmaxf(mx, g_b[i * NU + j]);
    red[t] = mx; __syncthreads();
    for (int o = 64; o > 0; o >>= 1) {
        if (t < o) red[t] = fmaxf(red[t], red[t + o]);
        __syncthreads();
    }
    mx = red[0]; __syncthreads();
    float sum = 0.0f;
    for (int i = t; i < INCH; i += 128) sum += __expf(g_b[i * NU + j] - mx);
    red[t] = sum; __syncthreads();
    for (int o = 64; o > 0; o >>= 1) {
        if (t < o) red[t] += red[t + o];
        __syncthreads();
    }
    float inv = 1.0f / red[0];
    for (int i = t; i < INCH; i += 128)
        g_c[i * NU + j] = __expf(g_b[i * NU + j] - mx) * inv;
}

// ===========================================================================
// GEMM1 (warp mma.sync bf16, 3-product hi/lo split over K'=384):
//   A' = [hi | hi | lo],  B' = [hi | lo | hi]  ->  hh + hl + lh  (drop ll ~2^-18)
// spart[ky][b][ju] = x[m0..+128, chunk] @ (c ⊙ W)[chunk, 160]
// CTA tile M=128 x N=160 x K'=384; 8 warps in 4(M) x 2(N); warp tile 32x80.
__global__ __launch_bounds__(256, 1) void gemm1mma_k(const float* __restrict__ x) {
    extern __shared__ char smem[];
    __nv_bfloat16* As = reinterpret_cast<__nv_bfloat16*>(smem);               // [128][KP]
    __nv_bfloat16* Bs = reinterpret_cast<__nv_bfloat16*>(smem + ASM_BYTES);   // [160][KP]
    const int tid = threadIdx.x;
    const int m0 = blockIdx.x * 128;
    const int ky = blockIdx.y;
    const int kb = ky * KCH;
    const int i0 = kb % INCH;               // chunk stays within one k-slice (1152=9*128)

    // ---- load A: fp32 -> hi at c, hi at 128+c, lo at 256+c
#pragma unroll
    for (int it = 0; it < 16; it++) {
        int idx = tid + it * 256;           // 4096 float4 slots
        int row = idx >> 5;
        int c4 = (idx & 31) * 4;
        float4 v = *reinterpret_cast<const float4*>(&x[(m0 + row) * KI + kb + c4]);
        __nv_bfloat16 h[4], l[4];
        split_bf16(v.x, h[0], l[0]);
        split_bf16(v.y, h[1], l[1]);
        split_bf16(v.z, h[2], l[2]);
        split_bf16(v.w, h[3], l[3]);
        uint2 hp = *reinterpret_cast<uint2*>(h);
        uint2 lp = *reinterpret_cast<uint2*>(l);
        *reinterpret_cast<uint2*>(&As[row * KP + c4]) = hp;
        *reinterpret_cast<uint2*>(&As[row * KP + 128 + c4]) = hp;
        *reinterpret_cast<uint2*>(&As[row * KP + 256 + c4]) = lp;
    }
    // ---- load B: fp32 W, fused c-scale -> hi at c, lo at 128+c, hi at 256+c
#pragma unroll
    for (int it = 0; it < 20; it++) {
        int idx = tid + it * 256;           // 5120 float4 slots
        int ju = idx >> 5;
        int c4 = (idx & 31) * 4;
        int j = ju >> 4;
        float4 v = *reinterpret_cast<const float4*>(&g_Wtt[ju * KI + kb + c4]);
        const float* cp = &g_c[(i0 + c4) * NU + j];
        float p[4] = {v.x * cp[0], v.y * cp[NU], v.z * cp[2 * NU], v.w * cp[3 * NU]};
        __nv_bfloat16 h[4], l[4];
#pragma unroll
        for (int q = 0; q < 4; q++) split_bf16(p[q], h[q], l[q]);
        uint2 hp = *reinterpret_cast<uint2*>(h);
        uint2 lp = *reinterpret_cast<uint2*>(l);
        *reinterpret_cast<uint2*>(&Bs[ju * KP + c4]) = hp;
        *reinterpret_cast<uint2*>(&Bs[ju * KP + 128 + c4]) = lp;
        *reinterpret_cast<uint2*>(&Bs[ju * KP + 256 + c4]) = hp;
    }
    __syncthreads();

    const int lane = tid & 31;
    const int wid = tid >> 5;
    const int m_off = (wid & 3) * 32;
    const int n_off = (wid >> 2) * 80;

    const uint32_t sbA = s2u(As);
    const uint32_t sbB = s2u(Bs);
    // A x4: lanes 0-15 -> rows m_off+(lane&15); lanes 16-31 -> same rows, k+8
    uint32_t aAddr = sbA + ((m_off + (lane & 15)) * KP + (lane >> 4) * 8) * 2;
    // B x4: rows n_off + (lane&7) + ((lane>>4)<<3); col +8 when bit3 set
    uint32_t bAddr = sbB + ((n_off + (lane & 7) + ((lane >> 4) << 3)) * KP
                            + ((lane >> 3) & 1) * 8) * 2;

    float acc[2][10][4];
#pragma unroll
    for (int mf = 0; mf < 2; mf++)
#pragma unroll
        for (int nf = 0; nf < 10; nf++)
#pragma unroll
            for (int q = 0; q < 4; q++) acc[mf][nf][q] = 0.0f;

#pragma unroll 4
    for (int ks = 0; ks < KSTEPS; ks++) {
        const int k0 = ks * 16;
        uint32_t a0[4], a1[4];
        ldm_x4(a0, aAddr + k0 * 2);
        ldm_x4(a1, aAddr + (16 * KP + k0) * 2);
#pragma unroll
        for (int p = 0; p < 5; p++) {
            uint32_t b[4];
            ldm_x4(b, bAddr + (16 * p * KP + k0) * 2);
            mma16816(acc[0][2 * p], a0, b);
            mma16816(acc[0][2 * p + 1], a0, b + 2);
            mma16816(acc[1][2 * p], a1, b);
            mma16816(acc[1][2 * p + 1], a1, b + 2);
        }
    }

    // ---- epilogue: D frag (m16n8) -> spart[ky][b][ju]
    float* out = &g_spart[ky * (BB * JU)];
    const int mrow = m0 + m_off + (lane >> 2);
    const int ncol = n_off + 2 * (lane & 3);
#pragma unroll
    for (int mf = 0; mf < 2; mf++)
#pragma unroll
        for (int nf = 0; nf < 10; nf++) {
            const float* d = acc[mf][nf];
            int m = mrow + 16 * mf;
            int n = ncol + 8 * nf;
            *reinterpret_cast<float2*>(&out[m * JU + n]) = make_float2(d[0], d[1]);
            *reinterpret_cast<float2*>(&out[(m + 8) * JU + n]) = make_float2(d[2], d[3]);
        }
}

// reduce split-K partials: s = sum over KSPLIT of s_part (float4, coalesced)
__global__ void reduceS_k() {
    int idx = blockIdx.x * blockDim.x + threadIdx.x;   // over BB*JU/4
    if (idx >= BB * JU / 4) return;
    float4 acc = make_float4(0.f, 0.f, 0.f, 0.f);
#pragma unroll 8
    for (int ks = 0; ks < KSPLIT; ks++) {
        float4 v = *reinterpret_cast<const float4*>(&g_spart[ks * (BB * JU) + idx * 4]);
        acc.x += v.x; acc.y += v.y; acc.z += v.z; acc.w += v.w;
    }
    *reinterpret_cast<float4*>(&g_s[idx * 4]) = acc;
}

// squash: mag_sq over j (num_units axis). Writes g_v, optionally also d_out.
__global__ void squash_k(float* __restrict__ out, int writeOut) {
    int idx = blockIdx.x * blockDim.x + threadIdx.x;   // (b,u): 512*16
    if (idx >= BB * US) return;
    int b = idx >> 4;
    int u = idx & 15;
    float sv[NU];
    float msq = 0.0f;
#pragma unroll
    for (int j = 0; j < NU; j++) {
        sv[j] = g_s[b * JU + j * US + u];
        msq += sv[j] * sv[j];
    }
    float mag = sqrtf(msq);
    float sc = msq / ((BETA + msq) * mag);
    if (writeOut) {
#pragma unroll
        for (int j = 0; j < NU; j++) out[b * JU + j * US + u] = sc * sv[j];
    } else {
#pragma unroll
        for (int j = 0; j < NU; j++) g_v[b * JU + j * US + u] = sc * sv[j];
    }
}

// ===========================================================================
// GEMM2 (round-5 FFMA2): Gpart[s] = x^T chunk @ v chunk, pipelined 8x10.
__global__ __launch_bounds__(256, 2) void gemm2_k(const float* __restrict__ x) {
    __shared__ float As[2][16][MT];
    __shared__ float Bs[2][16][JU];
    const int m0 = blockIdx.x * MT;
    const int kb0 = blockIdx.y * BCHUNK;
    const int tid = threadIdx.x;
    const int trow = tid >> 4;
    const int tcol = tid & 15;
    const int nb = tcol * 10;
    const int aK = tid >> 5;
    const int aM = (tid & 31) * 4;
    const int bRow = tid >> 4;

    unsigned long long acc[8][5];
#pragma unroll
    for (int r = 0; r < 8; r++)
#pragma unroll
        for (int c = 0; c < 5; c++) acc[r][c] = 0ULL;

    float4 rA0, rA1;
    float2 rB[5];

#define G2_FETCH(kb)                                                              \
    {                                                                             \
        rA0 = *reinterpret_cast<const float4*>(&x[((kb) + aK) * KI + m0 + aM]);   \
        rA1 = *reinterpret_cast<const float4*>(&x[((kb) + aK + 8) * KI + m0 + aM]);\
        const float* bp = &g_v[((kb) + bRow) * JU + nb];                          \
        rB[0] = *reinterpret_cast<const float2*>(bp + 0);                         \
        rB[1] = *reinterpret_cast<const float2*>(bp + 2);                         \
        rB[2] = *reinterpret_cast<const float2*>(bp + 4);                         \
        rB[3] = *reinterpret_cast<const float2*>(bp + 6);                         \
        rB[4] = *reinterpret_cast<const float2*>(bp + 8);                         \
    }
#define G2_STORE(buf)                                                             \
    {                                                                             \
        *reinterpret_cast<float4*>(&As[buf][aK][aM]) = rA0;                       \
        *reinterpret_cast<float4*>(&As[buf][aK + 8][aM]) = rA1;                   \
        _Pragma("unroll")                                                         \
        for (int c = 0; c < 5; c++)                                               \
            *reinterpret_cast<float2*>(&Bs[buf][bRow][nb + 2 * c]) = rB[c];       \
    }

    G2_FETCH(kb0);
    G2_STORE(0);
    __syncthreads();

#pragma unroll 1
    for (int t = 0; t < BCHUNK / 16; t++) {
        const int buf = t & 1;
        if (t + 1 < BCHUNK / 16) G2_FETCH(kb0 + (t + 1) * 16);
#pragma unroll
        for (int kk = 0; kk < 16; kk++) {
            float4 a0 = *reinterpret_cast<const float4*>(&As[buf][kk][trow * 8]);
            float4 a1 = *reinterpret_cast<const float4*>(&As[buf][kk][trow * 8 + 4]);
            unsigned long long ap[8];
            ap[0] = pk2(a0.x); ap[1] = pk2(a0.y); ap[2] = pk2(a0.z); ap[3] = pk2(a0.w);
            ap[4] = pk2(a1.x); ap[5] = pk2(a1.y); ap[6] = pk2(a1.z); ap[7] = pk2(a1.w);
#pragma unroll
            for (int c = 0; c < 5; c++) {
                unsigned long long bp =
                    *reinterpret_cast<const unsigned long long*>(&Bs[buf][kk][nb + 2 * c]);
#pragma unroll
                for (int r = 0; r < 8; r++) ffma2(acc[r][c], ap[r], bp);
            }
        }
        if (t + 1 < BCHUNK / 16) {
            G2_STORE(buf ^ 1);
            __syncthreads();
        }
    }

    float* out = g_Gpart[blockIdx.y];
#pragma unroll
    for (int r = 0; r < 8; r++)
#pragma unroll
        for (int c = 0; c < 5; c++)
            *reinterpret_cast<unsigned long long*>(
                &out[(m0 + trow * 8 + r) * JU + nb + 2 * c]) = acc[r][c];
#undef G2_FETCH
#undef G2_STORE
}

// b[i,j] = (1/B) * sum_{k,u} Wt * (ΣGpart)
__global__ void bupdate_k() {
    int gw = (blockIdx.x * blockDim.x + threadIdx.x) >> 5;
    int lane = threadIdx.x & 31;
    if (gw >= INCH * NU) return;
    int i = gw / NU;
    int j = gw - i * NU;
    int k = lane >> 2;
    int u = (lane & 3) * 4;
    int idx = (k * INCH + i) * JU + j * US + u;
    float4 w = *reinterpret_cast<const float4*>(&g_Wt[idx]);
    float4 g = *reinterpret_cast<const float4*>(&g_Gpart[0][idx]);
#pragma unroll
    for (int s = 1; s < BSPLIT; s++) {
        float4 gs = *reinterpret_cast<const float4*>(&g_Gpart[s][idx]);
        g.x += gs.x; g.y += gs.y; g.z += gs.z; g.w += gs.w;
    }
    float acc = w.x * g.x + w.y * g.y + w.z * g.z + w.w * g.w;
#pragma unroll
    for (int o = 16; o > 0; o >>= 1) acc += __shfl_xor_sync(0xffffffffu, acc, o);
    if (lane == 0) g_b[i * NU + j] = acc * (1.0f / (float)BB);
}

// ---------------------------------------------------------------------------
extern "C" void kernel_launch(void* const* d_in, const int* in_sizes, int n_in,
                              void* d_out, int out_size) {
    const float* x = (const float*)d_in[0];
    const float* W = (const float*)d_in[1];
    if (n_in >= 2 && in_sizes[0] == INCH * NU * US * INU) {
        const float* t = x; x = W; W = t;
    }
    float* out = (float*)d_out;

    cudaFuncSetAttribute(gemm1mma_k, cudaFuncAttributeMaxDynamicSharedMemorySize, SMEM_G1);

    zero_b_k<<<(INCH * NU + 255) / 256, 256>>>();
    transposeW_k<<<(INCH * JU + 255) / 256, 256>>>(W);

    for (int t = 0; t < 3; t++) {
        softmax_k<<<NU, 128>>>();
        gemm1mma_k<<<dim3(BB / 128, KSPLIT), 256, SMEM_G1>>>(x);
        reduceS_k<<<(BB * JU / 4 + 127) / 128, 128>>>();
        squash_k<<<(BB * US + 255) / 256, 256>>>(out, t == 2 ? 1 : 0);
        if (t < 2) {
            gemm2_k<<<dim3(KI / MT, BSPLIT), 256>>>(x);
            bupdate_k<<<(INCH * NU * 32) / 256, 256>>>();
        }
    }
}